// round 8
// baseline (speedup 1.0000x reference)
#include <cuda_runtime.h>
#include <math.h>

// ---------------------------------------------------------------------------
// CausalSelfAttention: x -> (QKV proj + RoPE) -> flash attention -> out proj
// B=2, T=2048, C=1024, nh=16, hs=64. fp32 with packed f32x2 (FFMA2) math.
// R7: 512-thread CTAs everywhere (16 warps/SM = 4/SMSP for latency hiding);
// attn keeps no-max softmax, no launch-bounds reg cap (no spills).
// ---------------------------------------------------------------------------

#define NH     16
#define HS     64
#define TSEQ   2048
#define CEMB   1024
#define BROWS  4096
#define LN1E4  9.210340371976184f
#define ASTR   132     // GEMM smem row stride (floats)
#define QSTR   132     // attn Q/P smem row stride
#define KSTR   68      // attn K/V smem row stride

typedef unsigned long long u64;

// ---- packed f32x2 helpers (sm_100+ PTX) -----------------------------------
__device__ __forceinline__ void fma2(u64& c, u64 a, u64 b) {
    asm("fma.rn.f32x2 %0, %1, %2, %0;" : "+l"(c) : "l"(a), "l"(b));
}
__device__ __forceinline__ void add2(u64& c, u64 a) {
    asm("add.rn.f32x2 %0, %0, %1;" : "+l"(c) : "l"(a), "l"(a));
}
__device__ __forceinline__ u64 bc2(float v) {
    u64 r; asm("mov.b64 %0, {%1, %1};" : "=l"(r) : "f"(v)); return r;
}
__device__ __forceinline__ u64 pk2(float lo, float hi) {
    u64 r; asm("mov.b64 %0, {%1, %2};" : "=l"(r) : "f"(lo), "f"(hi)); return r;
}
__device__ __forceinline__ float2 up2(u64 v) {
    float2 f; asm("mov.b64 {%0, %1}, %2;" : "=f"(f.x), "=f"(f.y) : "l"(v)); return f;
}

// Scratch (allocation-free): Q/K/V in (b,h,t,d) layout, y in (b,t,c) layout.
__device__ __align__(16) float g_q[2 * NH * TSEQ * HS];
__device__ __align__(16) float g_k[2 * NH * TSEQ * HS];
__device__ __align__(16) float g_v[2 * NH * TSEQ * HS];
__device__ __align__(16) float g_y[2 * TSEQ * CEMB];

// Stage this thread's 4 k-values of one 128-row operand slice.
__device__ __forceinline__ void stage4(float* S, int ks_, int rs_, float4 a)
{
    S[(ks_ + 0) * ASTR + rs_] = a.x;
    S[(ks_ + 1) * ASTR + rs_] = a.y;
    S[(ks_ + 2) * ASTR + rs_] = a.z;
    S[(ks_ + 3) * ASTR + rs_] = a.w;
}

// ---------------------------------------------------------------------------
// Kernel 1: QKV projection.  out[r,c] = sum_k x[r,k] * W[c,k] + b[c]
// 128x128 tile, BK=16, 512 threads, 8x4 microtile, FFMA2 row-pair accs.
// Double-buffered smem, one __syncthreads per K-tile.
// Epilogue: bias + RoPE (Q,K), scatter to (b,h,t,d).
// ---------------------------------------------------------------------------
__global__ __launch_bounds__(512, 1) void qkv_gemm(
    const float* __restrict__ x,
    const float* __restrict__ Wq, const float* __restrict__ bq,
    const float* __restrict__ Wk, const float* __restrict__ bk,
    const float* __restrict__ Wv, const float* __restrict__ bv)
{
    const int z = blockIdx.z;
    const float* W    = (z == 0) ? Wq : (z == 1) ? Wk : Wv;
    const float* bias = (z == 0) ? bq : (z == 1) ? bk : bv;
    float* out        = (z == 0) ? g_q : (z == 1) ? g_k : g_v;

    __shared__ __align__(16) float As[2][16 * ASTR];
    __shared__ __align__(16) float Bs[2][16 * ASTR];

    const int tid = threadIdx.x;
    const int tx = tid & 31;            // col group: cols tx*4 .. tx*4+3
    const int ty = tid >> 5;            // row group: rows ty*8 .. ty*8+7
    const int row0 = blockIdx.y * 128;
    const int col0 = blockIdx.x * 128;

    const int rs_ = tid >> 2;           // staging row 0..127
    const int ks_ = (tid & 3) * 4;      // staging k offset

    const float* ap = x + (size_t)(row0 + rs_) * CEMB + ks_;
    const float* bp = W + (size_t)(col0 + rs_) * CEMB + ks_;

    u64 acc[4][4];                      // [row-pair][col], packed f32x2
    #pragma unroll
    for (int p = 0; p < 4; p++)
        #pragma unroll
        for (int j = 0; j < 4; j++) acc[p][j] = 0ULL;

    float4 pa = *(const float4*)(ap);
    float4 pb = *(const float4*)(bp);
    stage4(&As[0][0], ks_, rs_, pa);
    stage4(&Bs[0][0], ks_, rs_, pb);
    __syncthreads();

    int buf = 0;
    #pragma unroll 1
    for (int kt = 0; kt < CEMB; kt += 16) {
        const bool more = (kt + 16 < CEMB);
        if (more) {                     // prefetch next tile under compute
            pa = *(const float4*)(ap + kt + 16);
            pb = *(const float4*)(bp + kt + 16);
        }
        const float* Ac = &As[buf][0];
        const float* Bc = &Bs[buf][0];
        #pragma unroll
        for (int kk = 0; kk < 16; kk++) {
            const float* abase = Ac + kk * ASTR + ty * 8;
            ulonglong2 aP = *(const ulonglong2*)abase;       // rows 0..3
            ulonglong2 aQ = *(const ulonglong2*)(abase + 4); // rows 4..7
            float4 b0 = *(const float4*)(Bc + kk * ASTR + tx * 4);
            u64 aa[4] = {aP.x, aP.y, aQ.x, aQ.y};
            u64 bb[4] = {bc2(b0.x), bc2(b0.y), bc2(b0.z), bc2(b0.w)};
            #pragma unroll
            for (int p = 0; p < 4; p++)
                #pragma unroll
                for (int j = 0; j < 4; j++)
                    fma2(acc[p][j], aa[p], bb[j]);
        }
        if (more) {
            stage4(&As[buf ^ 1][0], ks_, rs_, pa);
            stage4(&Bs[buf ^ 1][0], ks_, rs_, pb);
            __syncthreads();
            buf ^= 1;
        }
    }

    // Epilogue: bias, RoPE (Q,K), scatter to (b, h, t, d).
    const int col = col0 + tx * 4;
    const int h = col >> 6;             // global head index
    const int d0 = col & 63;
    float4 bb4 = *(const float4*)&bias[col];
    float bvv[4] = {bb4.x, bb4.y, bb4.z, bb4.w};

    float th0 = 0.f, th1 = 0.f;
    if (z < 2) {
        th0 = expf(-((float)d0)       * (LN1E4 / 64.0f));
        th1 = expf(-((float)(d0 + 2)) * (LN1E4 / 64.0f));
    }

    #pragma unroll
    for (int p = 0; p < 4; p++) {
        #pragma unroll
        for (int e = 0; e < 2; e++) {
            float v[4];
            #pragma unroll
            for (int j = 0; j < 4; j++) {
                float2 f = up2(acc[p][j]);
                v[j] = ((e == 0) ? f.x : f.y) + bvv[j];
            }
            int row = row0 + ty * 8 + 2 * p + e;
            int b = row >> 11;
            int t = row & 2047;
            if (z < 2) {
                float c0, s0, c1, s1;
                sincosf((float)t * th0, &s0, &c0);
                sincosf((float)t * th1, &s1, &c1);
                float r0 = v[0] * c0 - v[1] * s0, r1 = v[0] * s0 + v[1] * c0;
                float r2 = v[2] * c1 - v[3] * s1, r3 = v[2] * s1 + v[3] * c1;
                v[0] = r0; v[1] = r1; v[2] = r2; v[3] = r3;
            }
            float4 ov = {v[0], v[1], v[2], v[3]};
            *(float4*)&out[(((size_t)b * NH + h) * TSEQ + t) * HS + d0] = ov;
        }
    }
}

// ---------------------------------------------------------------------------
// Kernel 2: flash attention (fp32/FFMA2, causal), no-max softmax
// (scores bounded ~|q||k|/8; exp safe in fp32; l reduced once at the end).
// Br=128 q-rows, Bc=64 keys. 512 threads, 4q x 4k microtile, row-pair FFMA2.
// ---------------------------------------------------------------------------
#define ATTN_SMEM ((64 * QSTR * 2 + 64 * KSTR * 2) * 4)   // 102400 bytes

__global__ __launch_bounds__(512, 1) void attn_kernel()
{
    extern __shared__ __align__(16) float sm[];
    float* Qs = sm;                  // [d][q]  64 x 132, pre-scaled
    float* Ks = Qs + 64 * QSTR;      // [d][k]  64 x 68
    float* Ps = Ks + 64 * KSTR;      // [k][q]  64 x 132
    float* Vs = Ps + 64 * QSTR;      // [k][d]  64 x 68

    const int tid = threadIdx.x;
    const int tx = tid & 15;         // k/d col group: tx*4 .. tx*4+3
    const int ty = tid >> 4;         // q rows ty*4 .. ty*4+3 (ty 0..31)
    const int qt = (gridDim.x - 1) - blockIdx.x;    // heavy tiles first
    const int bh = blockIdx.y;

    const float* qp = g_q + (size_t)bh * TSEQ * HS;
    const float* kp = g_k + (size_t)bh * TSEQ * HS;
    const float* vp = g_v + (size_t)bh * TSEQ * HS;

    const int q0 = qt * 128;

    // Load Q tile transposed, pre-scaled by 1/sqrt(hs)
    #pragma unroll
    for (int jj = 0; jj < 4; jj++) {
        int idx = tid + jj * 512;
        int r = idx >> 4;
        int c4 = (idx & 15) * 4;
        float4 qv = *(const float4*)&qp[(size_t)(q0 + r) * HS + c4];
        Qs[(c4 + 0) * QSTR + r] = qv.x * 0.125f;
        Qs[(c4 + 1) * QSTR + r] = qv.y * 0.125f;
        Qs[(c4 + 2) * QSTR + r] = qv.z * 0.125f;
        Qs[(c4 + 3) * QSTR + r] = qv.w * 0.125f;
    }

    // Stage K/V tile 0
    float4 kreg[2], vreg[2];
    #pragma unroll
    for (int jj = 0; jj < 2; jj++) {
        int idx = tid + jj * 512;
        int r = idx >> 4;
        int c4 = (idx & 15) * 4;
        kreg[jj] = *(const float4*)&kp[(size_t)r * HS + c4];
        vreg[jj] = *(const float4*)&vp[(size_t)r * HS + c4];
    }
    #pragma unroll
    for (int jj = 0; jj < 2; jj++) {
        int idx = tid + jj * 512;
        int r = idx >> 4;
        int c4 = (idx & 15) * 4;
        Ks[(c4 + 0) * KSTR + r] = kreg[jj].x;
        Ks[(c4 + 1) * KSTR + r] = kreg[jj].y;
        Ks[(c4 + 2) * KSTR + r] = kreg[jj].z;
        Ks[(c4 + 3) * KSTR + r] = kreg[jj].w;
        *(float4*)&Vs[r * KSTR + c4] = vreg[jj];
    }

    u64 O[2][4];                     // [row-pair][d-col], packed f32x2
    u64 l2[2];                       // packed per-lane partial row sums
    #pragma unroll
    for (int p = 0; p < 2; p++) {
        l2[p] = 0ULL;
        #pragma unroll
        for (int j = 0; j < 4; j++) O[p][j] = 0ULL;
    }

    const int ktmax = 2 * qt + 1;
    __syncthreads();

    for (int kt = 0; kt <= ktmax; kt++) {
        // S = (Q/8) K^T, packed over q-row pairs
        u64 s2[2][4];
        #pragma unroll
        for (int p = 0; p < 2; p++)
            #pragma unroll
            for (int j = 0; j < 4; j++) s2[p][j] = 0ULL;
        #pragma unroll 8
        for (int d = 0; d < 64; d++) {
            ulonglong2 aA = *(const ulonglong2*)&Qs[d * QSTR + ty * 4];
            float4 kv = *(const float4*)&Ks[d * KSTR + tx * 4];
            u64 bb[4] = {bc2(kv.x), bc2(kv.y), bc2(kv.z), bc2(kv.w)};
            #pragma unroll
            for (int j = 0; j < 4; j++) {
                fma2(s2[0][j], aA.x, bb[j]);
                fma2(s2[1][j], aA.y, bb[j]);
            }
        }

        // Prefetch next K/V tile into registers (hidden under exp + PV)
        if (kt < ktmax) {
            const int kn = (kt + 1) * 64;
            #pragma unroll
            for (int jj = 0; jj < 2; jj++) {
                int idx = tid + jj * 512;
                int r = idx >> 4;
                int c4 = (idx & 15) * 4;
                kreg[jj] = *(const float4*)&kp[(size_t)(kn + r) * HS + c4];
                vreg[jj] = *(const float4*)&vp[(size_t)(kn + r) * HS + c4];
            }
        }

        // exp (no max subtraction), causal mask, l accumulate, store P
        const int k0 = kt * 64;
        const bool diag = (kt >= 2 * qt);
        #pragma unroll
        for (int p = 0; p < 2; p++) {
            float2 f[4];
            #pragma unroll
            for (int j = 0; j < 4; j++) f[j] = up2(s2[p][j]);
            const int rb = ty * 4 + 2 * p;
            if (diag) {
                const int r0 = q0 + rb, r1 = r0 + 1;
                #pragma unroll
                for (int j = 0; j < 4; j++) {
                    int c = k0 + tx * 4 + j;
                    if (c > r0) f[j].x = -1e30f;
                    if (c > r1) f[j].y = -1e30f;
                }
            }
            #pragma unroll
            for (int j = 0; j < 4; j++) {
                u64 pe = pk2(__expf(f[j].x), __expf(f[j].y));
                asm("add.rn.f32x2 %0, %0, %1;" : "+l"(l2[p]) : "l"(pe));
                *(u64*)&Ps[(tx * 4 + j) * QSTR + rb] = pe;
            }
        }
        __syncthreads();             // Ps visible; everyone done with Ks

        // O += P V
        #pragma unroll 8
        for (int kk = 0; kk < 64; kk++) {
            ulonglong2 aA = *(const ulonglong2*)&Ps[kk * QSTR + ty * 4];
            float4 vv = *(const float4*)&Vs[kk * KSTR + tx * 4];
            u64 bb[4] = {bc2(vv.x), bc2(vv.y), bc2(vv.z), bc2(vv.w)};
            #pragma unroll
            for (int j = 0; j < 4; j++) {
                fma2(O[0][j], aA.x, bb[j]);
                fma2(O[1][j], aA.y, bb[j]);
            }
        }
        __syncthreads();             // Vs/Ps reads done

        if (kt < ktmax) {            // stage next tile
            #pragma unroll
            for (int jj = 0; jj < 2; jj++) {
                int idx = tid + jj * 512;
                int r = idx >> 4;
                int c4 = (idx & 15) * 4;
                Ks[(c4 + 0) * KSTR + r] = kreg[jj].x;
                Ks[(c4 + 1) * KSTR + r] = kreg[jj].y;
                Ks[(c4 + 2) * KSTR + r] = kreg[jj].z;
                Ks[(c4 + 3) * KSTR + r] = kreg[jj].w;
                *(float4*)&Vs[r * KSTR + c4] = vreg[jj];
            }
            __syncthreads();         // staging visible for next S
        }
    }

    // Final l reduction across the 16 tx lanes (once)
    float l[4];
    #pragma unroll
    for (int p = 0; p < 2; p++) {
        float2 f = up2(l2[p]);
        l[2 * p] = f.x;
        l[2 * p + 1] = f.y;
    }
    #pragma unroll
    for (int i = 0; i < 4; i++)
        #pragma unroll
        for (int off = 8; off >= 1; off >>= 1)
            l[i] += __shfl_xor_sync(0xffffffffu, l[i], off);

    // Normalize, write y in (b, t, c) layout for the output projection
    const int b = bh >> 4, h = bh & 15;
    #pragma unroll
    for (int p = 0; p < 2; p++) {
        float2 f0 = up2(O[p][0]);
        float2 f1 = up2(O[p][1]);
        float2 f2 = up2(O[p][2]);
        float2 f3 = up2(O[p][3]);
        float inv0 = 1.0f / l[2 * p];
        float inv1 = 1.0f / l[2 * p + 1];
        int t0 = q0 + ty * 4 + 2 * p;
        float4 o0 = {f0.x * inv0, f1.x * inv0, f2.x * inv0, f3.x * inv0};
        float4 o1 = {f0.y * inv1, f1.y * inv1, f2.y * inv1, f3.y * inv1};
        *(float4*)&g_y[((size_t)b * TSEQ + t0) * CEMB + h * HS + tx * 4] = o0;
        *(float4*)&g_y[((size_t)b * TSEQ + t0 + 1) * CEMB + h * HS + tx * 4] = o1;
    }
}

// ---------------------------------------------------------------------------
// Kernel 3: output projection. Same 512-thread FFMA2 GEMM, bias epilogue.
// ---------------------------------------------------------------------------
__global__ __launch_bounds__(512, 1) void proj_gemm(
    const float* __restrict__ Wp, const float* __restrict__ bp,
    float* __restrict__ out)
{
    __shared__ __align__(16) float As[2][16 * ASTR];
    __shared__ __align__(16) float Bs[2][16 * ASTR];

    const int tid = threadIdx.x;
    const int tx = tid & 31;
    const int ty = tid >> 5;
    const int row0 = blockIdx.y * 128;
    const int col0 = blockIdx.x * 128;

    const int rs_ = tid >> 2;
    const int ks_ = (tid & 3) * 4;

    const float* ap = g_y + (size_t)(row0 + rs_) * CEMB + ks_;
    const float* bpW = Wp + (size_t)(col0 + rs_) * CEMB + ks_;

    u64 acc[4][4];
    #pragma unroll
    for (int p = 0; p < 4; p++)
        #pragma unroll
        for (int j = 0; j < 4; j++) acc[p][j] = 0ULL;

    float4 pa = *(const float4*)(ap);
    float4 pb = *(const float4*)(bpW);
    stage4(&As[0][0], ks_, rs_, pa);
    stage4(&Bs[0][0], ks_, rs_, pb);
    __syncthreads();

    int buf = 0;
    #pragma unroll 1
    for (int kt = 0; kt < CEMB; kt += 16) {
        const bool more = (kt + 16 < CEMB);
        if (more) {
            pa = *(const float4*)(ap + kt + 16);
            pb = *(const float4*)(bpW + kt + 16);
        }
        const float* Ac = &As[buf][0];
        const float* Bc = &Bs[buf][0];
        #pragma unroll
        for (int kk = 0; kk < 16; kk++) {
            const float* abase = Ac + kk * ASTR + ty * 8;
            ulonglong2 aP = *(const ulonglong2*)abase;
            ulonglong2 aQ = *(const ulonglong2*)(abase + 4);
            float4 b0 = *(const float4*)(Bc + kk * ASTR + tx * 4);
            u64 aa[4] = {aP.x, aP.y, aQ.x, aQ.y};
            u64 bb[4] = {bc2(b0.x), bc2(b0.y), bc2(b0.z), bc2(b0.w)};
            #pragma unroll
            for (int p = 0; p < 4; p++)
                #pragma unroll
                for (int j = 0; j < 4; j++)
                    fma2(acc[p][j], aa[p], bb[j]);
        }
        if (more) {
            stage4(&As[buf ^ 1][0], ks_, rs_, pa);
            stage4(&Bs[buf ^ 1][0], ks_, rs_, pb);
            __syncthreads();
            buf ^= 1;
        }
    }

    float4 bb4 = *(const float4*)&bp[col0 + tx * 4];
    float bvv[4] = {bb4.x, bb4.y, bb4.z, bb4.w};

    #pragma unroll
    for (int p = 0; p < 4; p++) {
        #pragma unroll
        for (int e = 0; e < 2; e++) {
            float v[4];
            #pragma unroll
            for (int j = 0; j < 4; j++) {
                float2 f = up2(acc[p][j]);
                v[j] = ((e == 0) ? f.x : f.y) + bvv[j];
            }
            size_t row = (size_t)(row0 + ty * 8 + 2 * p + e);
            float4 ov = {v[0], v[1], v[2], v[3]};
            *(float4*)&out[row * CEMB + col0 + tx * 4] = ov;
        }
    }
}

// ---------------------------------------------------------------------------
extern "C" void kernel_launch(void* const* d_in, const int* in_sizes, int n_in,
                              void* d_out, int out_size)
{
    const float* x  = (const float*)d_in[0];
    const float* Wq = (const float*)d_in[1];
    const float* bq = (const float*)d_in[2];
    const float* Wk = (const float*)d_in[3];
    const float* bk = (const float*)d_in[4];
    const float* Wv = (const float*)d_in[5];
    const float* bv = (const float*)d_in[6];
    const float* Wp = (const float*)d_in[7];
    const float* bp = (const float*)d_in[8];
    float* out = (float*)d_out;

    cudaFuncSetAttribute(attn_kernel,
                         cudaFuncAttributeMaxDynamicSharedMemorySize, ATTN_SMEM);

    qkv_gemm<<<dim3(CEMB / 128, BROWS / 128, 3), 512>>>(x, Wq, bq, Wk, bk, Wv, bv);
    attn_kernel<<<dim3(TSEQ / 128, 2 * NH), 512, ATTN_SMEM>>>();
    proj_gemm<<<dim3(CEMB / 128, BROWS / 128), 512>>>(Wp, bp, out);
}